// round 9
// baseline (speedup 1.0000x reference)
#include <cuda_runtime.h>

#define NNODES 100000
#define NEDGES 1600000
#define NREL 4
#define NKEYS (NREL * NNODES)   // composite key = dst*4 + rel

// Scratch (allocation-free per harness rules)
__device__ __align__(16) float g_S1[NREL * NNODES * 16];  // 25.6 MB
__device__ __align__(16) float g_S2[NREL * NNODES * 16];  // 25.6 MB
__device__ __align__(16) float g_S3[NREL * NNODES * 32];  // 51.2 MB
__device__ __align__(16) float g_h1[NNODES * 16];
__device__ __align__(16) float g_h2[NNODES * 32];
__device__ int g_bins[NKEYS];       // histogram
__device__ int g_off[NKEYS + 1];    // exclusive offsets (CSR)
__device__ int g_fill[NKEYS];       // fill cursors
__device__ int g_bsum[1024];        // scan block sums
__device__ int g_ssrc[NEDGES];      // src ids sorted by key

typedef unsigned long long ull;

__device__ __forceinline__ void ffma2(ull& acc, ull a, ull b) {
    asm("fma.rn.f32x2 %0, %1, %2, %0;" : "+l"(acc) : "l"(a), "l"(b));
}
__device__ __forceinline__ ull bcast2(float v) {
    ull r;
    unsigned int u = __float_as_uint(v);
    asm("mov.b64 %0, {%1, %1};" : "=l"(r) : "r"(u));
    return r;
}

// ---------------------------------------------------------------------------
// CSR build: histogram -> exclusive scan -> fill
// ---------------------------------------------------------------------------
__global__ void hist_kernel(const int* __restrict__ dst,
                            const int* __restrict__ et,
                            int* __restrict__ bins, int e) {
    int i = blockIdx.x * blockDim.x + threadIdx.x;
    if (i < e) atomicAdd(&bins[dst[i] * 4 + et[i]], 1);
}

__global__ void scan1_kernel(const int* __restrict__ bins,
                             int* __restrict__ off,
                             int* __restrict__ bsum, int nk) {
    __shared__ int sh[512];
    int t = threadIdx.x;
    int g = blockIdx.x * 512 + t;
    int v = (g < nk) ? bins[g] : 0;
    sh[t] = v;
    __syncthreads();
    for (int s = 1; s < 512; s <<= 1) {
        int add = (t >= s) ? sh[t - s] : 0;
        __syncthreads();
        sh[t] += add;
        __syncthreads();
    }
    if (g < nk) off[g] = sh[t] - v;           // exclusive (local)
    if (t == 511) bsum[blockIdx.x] = sh[511]; // block total
}

__global__ void scan2_kernel(int* __restrict__ bsum, int nb) {
    __shared__ int sh[1024];
    int t = threadIdx.x;
    int v = (t < nb) ? bsum[t] : 0;
    sh[t] = v;
    __syncthreads();
    for (int s = 1; s < 1024; s <<= 1) {
        int add = (t >= s) ? sh[t - s] : 0;
        __syncthreads();
        sh[t] += add;
        __syncthreads();
    }
    if (t < nb) bsum[t] = sh[t] - v;          // exclusive base per block
}

__global__ void scan3_kernel(int* __restrict__ off,
                             const int* __restrict__ bsum, int nk, int e) {
    int g = blockIdx.x * 512 + threadIdx.x;
    if (g < nk) off[g] += bsum[g >> 9];
    if (g == nk) off[g] = e;
}

__global__ void fill_kernel(const int* __restrict__ src,
                            const int* __restrict__ dst,
                            const int* __restrict__ et,
                            const int* __restrict__ off,
                            int* __restrict__ fill,
                            int* __restrict__ ssrc, int e) {
    int i = blockIdx.x * blockDim.x + threadIdx.x;
    if (i >= e) return;
    int key = dst[i] * 4 + et[i];
    int pos = off[key] + atomicAdd(&fill[key], 1);
    ssrc[pos] = src[i];
}

// ---------------------------------------------------------------------------
// Gather: S[r, node, :] = sum over CSR segment (no atomics, coalesced stores).
// Warp per node. C = DIN/2 lanes per feature row (float2), G = 32/C edge
// groups in flight. Relation via position vs sub-offsets (predicated adds).
// Software-pipelined src-id loads.
// ---------------------------------------------------------------------------
template <int DIN>
__global__ void __launch_bounds__(256)
gather_kernel(const float* __restrict__ h,    // [n, DIN]
              const int* __restrict__ off,    // [4n+1]
              const int* __restrict__ ssrc,   // [E]
              float* __restrict__ S, int n) {
    constexpr int C = DIN / 2;   // lanes per row (float2 components)
    constexpr int G = 32 / C;    // edges processed in parallel
    const int node = (blockIdx.x * 256 + threadIdx.x) >> 5;
    if (node >= n) return;
    const int lane = threadIdx.x & 31;
    const int c = lane % C;
    const int g = lane / C;

    const int o0 = __ldg(off + 4 * node);
    const int o1 = __ldg(off + 4 * node + 1);
    const int o2 = __ldg(off + 4 * node + 2);
    const int o3 = __ldg(off + 4 * node + 3);
    const int o4 = __ldg(off + 4 * node + 4);
    const int deg = o4 - o0;

    float2 a0 = {0.f, 0.f}, a1 = {0.f, 0.f}, a2 = {0.f, 0.f}, a3 = {0.f, 0.f};
    const float2* x2 = reinterpret_cast<const float2*>(h);

    int i = g;
    int s_cur = (i < deg) ? __ldg(ssrc + o0 + i) : 0;
    for (; i < deg; i += G) {
        const int inx = i + G;
        const int s_nxt = (inx < deg) ? __ldg(ssrc + o0 + inx) : 0;
        const int pos = o0 + i;
        const int r = (pos >= o1) + (pos >= o2) + (pos >= o3);
        const float2 f = __ldg(x2 + (size_t)s_cur * C + c);
        if (r == 0)      { a0.x += f.x; a0.y += f.y; }
        else if (r == 1) { a1.x += f.x; a1.y += f.y; }
        else if (r == 2) { a2.x += f.x; a2.y += f.y; }
        else             { a3.x += f.x; a3.y += f.y; }
        s_cur = s_nxt;
    }

    // Butterfly reduce across the G edge groups
#pragma unroll
    for (int m = C; m < 32; m <<= 1) {
        a0.x += __shfl_xor_sync(0xffffffffu, a0.x, m);
        a0.y += __shfl_xor_sync(0xffffffffu, a0.y, m);
        a1.x += __shfl_xor_sync(0xffffffffu, a1.x, m);
        a1.y += __shfl_xor_sync(0xffffffffu, a1.y, m);
        a2.x += __shfl_xor_sync(0xffffffffu, a2.x, m);
        a2.y += __shfl_xor_sync(0xffffffffu, a2.y, m);
        a3.x += __shfl_xor_sync(0xffffffffu, a3.x, m);
        a3.y += __shfl_xor_sync(0xffffffffu, a3.y, m);
    }

    if (g == 0) {
        // raw sums; combine divides by count (derived from off there too,
        // but scaling here saves combine work): store SUMS scaled to MEANS
        const float i0 = 1.0f / (float)max(o1 - o0, 1);
        const float i1 = 1.0f / (float)max(o2 - o1, 1);
        const float i2 = 1.0f / (float)max(o3 - o2, 1);
        const float i3 = 1.0f / (float)max(o4 - o3, 1);
        float2 m0 = {a0.x * i0, a0.y * i0};
        float2 m1 = {a1.x * i1, a1.y * i1};
        float2 m2 = {a2.x * i2, a2.y * i2};
        float2 m3 = {a3.x * i3, a3.y * i3};
        *reinterpret_cast<float2*>(S + ((size_t)0 * n + node) * DIN + 2 * c) = m0;
        *reinterpret_cast<float2*>(S + ((size_t)1 * n + node) * DIN + 2 * c) = m1;
        *reinterpret_cast<float2*>(S + ((size_t)2 * n + node) * DIN + 2 * c) = m2;
        *reinterpret_cast<float2*>(S + ((size_t)3 * n + node) * DIN + 2 * c) = m3;
    }
}

// ---------------------------------------------------------------------------
// Combine (persistent, R7 structure): S already holds MEANS, so no inv here.
//   out[i] = bias + x[i]@root + sum_r mean_r[i] @ W_r
// ---------------------------------------------------------------------------
template <int DIN, int DOUT, bool RELU>
__global__ void __launch_bounds__(256)
combine_kernel(const float* __restrict__ xin,   // [n, DIN]
               const float* __restrict__ S,     // [R, n, DIN] (means)
               const float* __restrict__ W,     // [R, DIN, DOUT]
               const float* __restrict__ root,  // [DIN, DOUT]
               const float* __restrict__ bias,  // [DOUT]
               float* __restrict__ out, int n) {
    constexpr int COLS  = 8;
    constexpr int SPLIT = DOUT / COLS;
    constexpr int NT    = 2;
    constexpr int NG    = 256 / SPLIT;
    constexpr int NPB   = NG * NT;
    constexpr int CH    = DIN / 4;
    constexpr int NC4   = 5 * CH;

    __shared__ __align__(16) float sw[5 * DIN * DOUT];
    const int tid = threadIdx.x;
    {
        const float4* r4 = reinterpret_cast<const float4*>(root);
        const float4* w4 = reinterpret_cast<const float4*>(W);
        float4* s4 = reinterpret_cast<float4*>(sw);
        for (int i = tid; i < DIN * DOUT / 4; i += 256) s4[i] = __ldg(r4 + i);
        for (int i = tid; i < NREL * DIN * DOUT / 4; i += 256)
            s4[DIN * DOUT / 4 + i] = __ldg(w4 + i);
    }
    __syncthreads();

    const int ng = tid / SPLIT;
    const int sp = tid % SPLIT;
    const float* wbase = sw + sp * COLS;
    const float4* x4 = reinterpret_cast<const float4*>(xin);
    const ull* bb = reinterpret_cast<const ull*>(bias + sp * COLS);

    for (int tile = blockIdx.x * NPB; tile < n; tile += gridDim.x * NPB) {
        int nodev[NT];
        bool valid[NT];
#pragma unroll
        for (int i = 0; i < NT; i++) {
            int nd = tile + ng + i * NG;
            valid[i] = nd < n;
            nodev[i] = valid[i] ? nd : 0;
        }

        ull acc[NT][4];
#pragma unroll
        for (int i = 0; i < NT; i++)
#pragma unroll
            for (int j = 0; j < 4; j++) acc[i][j] = bb[j];

        float4 vcur[NT], vnxt[NT];
#pragma unroll
        for (int i = 0; i < NT; i++)
            vcur[i] = __ldg(x4 + (size_t)nodev[i] * CH);

#pragma unroll
        for (int b = 0; b < NC4; b++) {
            const int rb = b / CH;
            const int c4 = b % CH;
            if (b + 1 < NC4) {
                const int rbn = (b + 1) / CH;
                const int c4n = (b + 1) % CH;
#pragma unroll
                for (int i = 0; i < NT; i++) {
                    const float* base = (rbn == 0)
                        ? xin + (size_t)nodev[i] * DIN
                        : S + ((size_t)(rbn - 1) * n + nodev[i]) * DIN;
                    vnxt[i] = __ldg(reinterpret_cast<const float4*>(base) + c4n);
                }
            }
            ulonglong2 w[4][2];
#pragma unroll
            for (int k = 0; k < 4; k++) {
                const ulonglong2* wp = reinterpret_cast<const ulonglong2*>(
                    wbase + (rb * DIN + c4 * 4 + k) * DOUT);
                w[k][0] = wp[0];
                w[k][1] = wp[1];
            }
#pragma unroll
            for (int k = 0; k < 4; k++) {
#pragma unroll
                for (int i = 0; i < NT; i++) {
                    const float vk = (k == 0) ? vcur[i].x : (k == 1) ? vcur[i].y
                                   : (k == 2) ? vcur[i].z : vcur[i].w;
                    const ull v2 = bcast2(vk);
                    ffma2(acc[i][0], v2, w[k][0].x);
                    ffma2(acc[i][1], v2, w[k][0].y);
                    ffma2(acc[i][2], v2, w[k][1].x);
                    ffma2(acc[i][3], v2, w[k][1].y);
                }
            }
#pragma unroll
            for (int i = 0; i < NT; i++) vcur[i] = vnxt[i];
        }

#pragma unroll
        for (int i = 0; i < NT; i++) {
            if (!valid[i]) continue;
            float* op = out + (size_t)nodev[i] * DOUT + sp * COLS;
#pragma unroll
            for (int j = 0; j < 4; j++) {
                float2 f = *reinterpret_cast<float2*>(&acc[i][j]);
                if (RELU) {
                    f.x = fmaxf(f.x, 0.0f);
                    f.y = fmaxf(f.y, 0.0f);
                }
                reinterpret_cast<float2*>(op)[j] = f;
            }
        }
    }
}

// ---------------------------------------------------------------------------
// Launcher: CSR build once -> (gather, combine) x 3 layers
// ---------------------------------------------------------------------------
extern "C" void kernel_launch(void* const* d_in, const int* in_sizes, int n_in,
                              void* d_out, int out_size) {
    const float* x     = (const float*)d_in[0];
    const int*   ei    = (const int*)d_in[1];   // [2, E]: src then dst
    const int*   et    = (const int*)d_in[2];
    const float* W1    = (const float*)d_in[3];
    const float* root1 = (const float*)d_in[4];
    const float* b1    = (const float*)d_in[5];
    const float* W2    = (const float*)d_in[6];
    const float* root2 = (const float*)d_in[7];
    const float* b2    = (const float*)d_in[8];
    const float* W3    = (const float*)d_in[9];
    const float* root3 = (const float*)d_in[10];
    const float* b3    = (const float*)d_in[11];
    float* out = (float*)d_out;

    const int n = in_sizes[0] / 16;
    const int e = in_sizes[2];
    const int nk = 4 * n;
    const int* src = ei;
    const int* dst = ei + e;

    float *pS1, *pS2, *pS3, *ph1, *ph2;
    int *pbins, *poff, *pfill, *pbsum, *pssrc;
    cudaGetSymbolAddress((void**)&pS1, g_S1);
    cudaGetSymbolAddress((void**)&pS2, g_S2);
    cudaGetSymbolAddress((void**)&pS3, g_S3);
    cudaGetSymbolAddress((void**)&ph1, g_h1);
    cudaGetSymbolAddress((void**)&ph2, g_h2);
    cudaGetSymbolAddress((void**)&pbins, g_bins);
    cudaGetSymbolAddress((void**)&poff, g_off);
    cudaGetSymbolAddress((void**)&pfill, g_fill);
    cudaGetSymbolAddress((void**)&pbsum, g_bsum);
    cudaGetSymbolAddress((void**)&pssrc, g_ssrc);

    // Small memsets only (3.2 MB total; S buffers fully overwritten by gather)
    cudaMemsetAsync(pbins, 0, sizeof(int) * nk);
    cudaMemsetAsync(pfill, 0, sizeof(int) * nk);

    const int TB = 256;
    const int NB = (nk + 511) / 512;   // scan blocks (782)

    // CSR build (once; shared by all 3 layers)
    hist_kernel<<<(e + TB - 1) / TB, TB>>>(dst, et, pbins, e);
    scan1_kernel<<<NB, 512>>>(pbins, poff, pbsum, nk);
    scan2_kernel<<<1, 1024>>>(pbsum, NB);
    scan3_kernel<<<(nk + 512) / 512, 512>>>(poff, pbsum, nk, e);
    fill_kernel<<<(e + TB - 1) / TB, TB>>>(src, dst, et, poff, pfill, pssrc, e);

    const int CGRID = 444;
    const int ggrid = (n * 32 + TB - 1) / TB;   // warp per node

    // Layer 1: 16 -> 16, relu
    gather_kernel<16><<<ggrid, TB>>>(x, poff, pssrc, pS1, n);
    combine_kernel<16, 16, true><<<CGRID, 256>>>(
        x, pS1, W1, root1, b1, ph1, n);

    // Layer 2: 16 -> 32, relu
    gather_kernel<16><<<ggrid, TB>>>(ph1, poff, pssrc, pS2, n);
    combine_kernel<16, 32, true><<<CGRID, 256>>>(
        ph1, pS2, W2, root2, b2, ph2, n);

    // Layer 3: 32 -> 64, no relu
    gather_kernel<32><<<ggrid, TB>>>(ph2, poff, pssrc, pS3, n);
    combine_kernel<32, 64, false><<<CGRID, 256>>>(
        ph2, pS3, W3, root3, b3, out, n);
}